// round 1
// baseline (speedup 1.0000x reference)
#include <cuda_runtime.h>

#define N_ROWS 524288
#define DIM 256
#define KDIM 256
#define NSEG 8192

// ---------------- scratch (device globals: no allocations allowed) ----------
__device__ float    g_seg_sum[NSEG * DIM];   // 8 MB
__device__ unsigned g_seg_max[NSEG * DIM];   // 8 MB (order-encoded float)
__device__ int      g_counts[NSEG];
__device__ float    g_out_seg[NSEG * DIM];   // 8 MB

// order-preserving float <-> uint encoding (monotonic under unsigned compare)
__device__ __forceinline__ unsigned enc_f(float f) {
    unsigned i = __float_as_uint(f);
    return (i & 0x80000000u) ? ~i : (i | 0x80000000u);
}
__device__ __forceinline__ float dec_f(unsigned u) {
    return __uint_as_float((u & 0x80000000u) ? (u & 0x7FFFFFFFu) : ~u);
}

// ---------------- init: reset scratch each launch (graph-replay safe) -------
__global__ void init_kernel() {
    int i = blockIdx.x * blockDim.x + threadIdx.x;
    if (i < NSEG * DIM) {
        g_seg_sum[i] = 0.0f;
        g_seg_max[i] = 0u;   // below enc of any real float; count==0 guards decode
    }
    if (i < NSEG) g_counts[i] = 0;
}

// ---------------- kernel A: fused GEMM (h = x W1^T + b1) + segmented sum/max
// tile: 128 rows x 128 cols, BK=32, 256 threads, 8x8 per-thread microtile
__global__ __launch_bounds__(256) void gemm_pool_kernel(
    const float* __restrict__ x,
    const int*   __restrict__ bidx,
    const float* __restrict__ W1,
    const float* __restrict__ b1)
{
    __shared__ union {
        struct { float a[32 * 128]; float b[32 * 128]; } g;  // GEMM staging (32 KB)
        float hs[128 * 64];                                   // epilogue staging (32 KB)
    } sm;
    __shared__ int segid[128];

    const int t     = threadIdx.x;
    const int tileM = blockIdx.x * 128;
    const int tileN = blockIdx.y * 128;
    const int tx    = t & 15;
    const int ty    = t >> 4;

    if (t < 128) segid[t] = bidx[tileM + t];

    float acc[8][8];
#pragma unroll
    for (int i = 0; i < 8; i++)
#pragma unroll
        for (int j = 0; j < 8; j++) acc[i][j] = 0.0f;

    for (int kt = 0; kt < KDIM; kt += 32) {
        __syncthreads();  // previous-iter smem reads done (also covers segid)
#pragma unroll
        for (int l = 0; l < 4; l++) {
            int g4  = l * 256 + t;       // 1024 float4 loads per operand
            int row = g4 >> 3;
            int kq  = g4 & 7;
            float4 va = *(const float4*)&x [(size_t)(tileM + row) * KDIM + kt + kq * 4];
            float4 vb = *(const float4*)&W1[(size_t)(tileN + row) * KDIM + kt + kq * 4];
            sm.g.a[(kq * 4 + 0) * 128 + row] = va.x;
            sm.g.a[(kq * 4 + 1) * 128 + row] = va.y;
            sm.g.a[(kq * 4 + 2) * 128 + row] = va.z;
            sm.g.a[(kq * 4 + 3) * 128 + row] = va.w;
            sm.g.b[(kq * 4 + 0) * 128 + row] = vb.x;
            sm.g.b[(kq * 4 + 1) * 128 + row] = vb.y;
            sm.g.b[(kq * 4 + 2) * 128 + row] = vb.z;
            sm.g.b[(kq * 4 + 3) * 128 + row] = vb.w;
        }
        __syncthreads();
#pragma unroll
        for (int kk = 0; kk < 32; kk++) {
            float af[8], bf[8];
            *(float4*)&af[0] = *(const float4*)&sm.g.a[kk * 128 + ty * 8];
            *(float4*)&af[4] = *(const float4*)&sm.g.a[kk * 128 + ty * 8 + 4];
            *(float4*)&bf[0] = *(const float4*)&sm.g.b[kk * 128 + tx * 8];
            *(float4*)&bf[4] = *(const float4*)&sm.g.b[kk * 128 + tx * 8 + 4];
#pragma unroll
            for (int i = 0; i < 8; i++)
#pragma unroll
                for (int j = 0; j < 8; j++)
                    acc[i][j] = fmaf(af[i], bf[j], acc[i][j]);
        }
    }

    // bias per column
    float bias[8];
#pragma unroll
    for (int j = 0; j < 8; j++) bias[j] = __ldg(&b1[tileN + tx * 8 + j]);

    const float NEG_INF = __int_as_float(0xff800000);

    // two 64-column chunks: stage in smem, reduce by sorted segment runs
    for (int c = 0; c < 2; c++) {
        __syncthreads();  // prior reads of sm done
        if ((tx >> 3) == c) {
#pragma unroll
            for (int i = 0; i < 8; i++)
#pragma unroll
                for (int j = 0; j < 8; j++)
                    sm.hs[(ty * 8 + i) * 64 + (tx & 7) * 8 + j] = acc[i][j] + bias[j];
        }
        __syncthreads();

        const int col  = t & 63;
        const int q    = t >> 6;        // 4 row-quarters of 32 rows
        const int colG = tileN + c * 64 + col;
        const int r0   = q * 32;
        const bool countLane = (blockIdx.y == 0) && (c == 0) && (col == 0);

        int   cur = segid[r0];
        float s   = 0.0f;
        float mx  = NEG_INF;
        int   run = 0;
#pragma unroll 4
        for (int r = 0; r < 32; r++) {
            int   sg = segid[r0 + r];
            float v  = sm.hs[(r0 + r) * 64 + col];
            if (sg != cur) {
                atomicAdd(&g_seg_sum[cur * DIM + colG], s);
                atomicMax(&g_seg_max[cur * DIM + colG], enc_f(mx));
                if (countLane) atomicAdd(&g_counts[cur], run);
                cur = sg; s = 0.0f; mx = NEG_INF; run = 0;
            }
            s += v;
            mx = fmaxf(mx, v);
            run++;
        }
        atomicAdd(&g_seg_sum[cur * DIM + colG], s);
        atomicMax(&g_seg_max[cur * DIM + colG], enc_f(mx));
        if (countLane) atomicAdd(&g_counts[cur], run);
    }
}

// ---------------- kernel B: finalize pooled feats + projection GEMM ---------
// out_seg[b, d] = bp[d] + sum_k xpool[b,k] * Wp[d,k],  K = 512
__global__ __launch_bounds__(256) void proj_kernel(
    const float* __restrict__ Wp,
    const float* __restrict__ bp)
{
    __shared__ float a_s[32 * 128];
    __shared__ float b_s[32 * 128];
    __shared__ float invc[128];
    __shared__ int   cnt[128];

    const int t     = threadIdx.x;
    const int tileM = blockIdx.x * 128;   // segment rows
    const int tileN = blockIdx.y * 128;   // output cols
    const int tx    = t & 15;
    const int ty    = t >> 4;

    if (t < 128) {
        int cn  = g_counts[tileM + t];
        cnt[t]  = cn;
        invc[t] = 1.0f / (float)max(cn, 1);
    }

    float acc[8][8];
#pragma unroll
    for (int i = 0; i < 8; i++)
#pragma unroll
        for (int j = 0; j < 8; j++) acc[i][j] = 0.0f;

    for (int kt = 0; kt < 2 * DIM; kt += 32) {
        __syncthreads();
#pragma unroll
        for (int l = 0; l < 4; l++) {
            int g4  = l * 256 + t;
            int row = g4 >> 3;
            int kq  = g4 & 7;
            float4 va;
            if (kt < DIM) {  // mean half
                va = *(const float4*)&g_seg_sum[(size_t)(tileM + row) * DIM + kt + kq * 4];
                float iv = invc[row];
                va.x *= iv; va.y *= iv; va.z *= iv; va.w *= iv;
            } else {         // max half
                uint4 u = *(const uint4*)&g_seg_max[(size_t)(tileM + row) * DIM + (kt - DIM) + kq * 4];
                if (cnt[row] > 0) {
                    va.x = dec_f(u.x); va.y = dec_f(u.y); va.z = dec_f(u.z); va.w = dec_f(u.w);
                } else {
                    va.x = va.y = va.z = va.w = 0.0f;
                }
            }
            float4 vb = *(const float4*)&Wp[(size_t)(tileN + row) * (2 * DIM) + kt + kq * 4];
            a_s[(kq * 4 + 0) * 128 + row] = va.x;
            a_s[(kq * 4 + 1) * 128 + row] = va.y;
            a_s[(kq * 4 + 2) * 128 + row] = va.z;
            a_s[(kq * 4 + 3) * 128 + row] = va.w;
            b_s[(kq * 4 + 0) * 128 + row] = vb.x;
            b_s[(kq * 4 + 1) * 128 + row] = vb.y;
            b_s[(kq * 4 + 2) * 128 + row] = vb.z;
            b_s[(kq * 4 + 3) * 128 + row] = vb.w;
        }
        __syncthreads();
#pragma unroll
        for (int kk = 0; kk < 32; kk++) {
            float af[8], bf[8];
            *(float4*)&af[0] = *(const float4*)&a_s[kk * 128 + ty * 8];
            *(float4*)&af[4] = *(const float4*)&a_s[kk * 128 + ty * 8 + 4];
            *(float4*)&bf[0] = *(const float4*)&b_s[kk * 128 + tx * 8];
            *(float4*)&bf[4] = *(const float4*)&b_s[kk * 128 + tx * 8 + 4];
#pragma unroll
            for (int i = 0; i < 8; i++)
#pragma unroll
                for (int j = 0; j < 8; j++)
                    acc[i][j] = fmaf(af[i], bf[j], acc[i][j]);
        }
    }

    float bias[8];
#pragma unroll
    for (int j = 0; j < 8; j++) bias[j] = __ldg(&bp[tileN + tx * 8 + j]);

#pragma unroll
    for (int i = 0; i < 8; i++) {
        float4 v0, v1;
        v0.x = acc[i][0] + bias[0]; v0.y = acc[i][1] + bias[1];
        v0.z = acc[i][2] + bias[2]; v0.w = acc[i][3] + bias[3];
        v1.x = acc[i][4] + bias[4]; v1.y = acc[i][5] + bias[5];
        v1.z = acc[i][6] + bias[6]; v1.w = acc[i][7] + bias[7];
        size_t base = (size_t)(tileM + ty * 8 + i) * DIM + tileN + tx * 8;
        *(float4*)&g_out_seg[base]     = v0;
        *(float4*)&g_out_seg[base + 4] = v1;
    }
}

// ---------------- kernel C: gather out[i] = out_seg[batch_index[i]] ---------
__global__ void gather_kernel(const int* __restrict__ bidx, float4* __restrict__ out) {
    int i   = blockIdx.x * blockDim.x + threadIdx.x;  // over N * 64 float4
    int row = i >> 6;
    int j   = i & 63;
    out[i] = ((const float4*)g_out_seg)[bidx[row] * 64 + j];
}

// ---------------- launch -----------------------------------------------------
extern "C" void kernel_launch(void* const* d_in, const int* in_sizes, int n_in,
                              void* d_out, int out_size) {
    const float* x    = (const float*)d_in[0];
    const int*   bidx = (const int*)  d_in[1];
    const float* W1   = (const float*)d_in[2];
    const float* b1   = (const float*)d_in[3];
    const float* Wp   = (const float*)d_in[4];
    const float* bp   = (const float*)d_in[5];
    float* out = (float*)d_out;

    init_kernel<<<(NSEG * DIM + 255) / 256, 256>>>();

    dim3 gA(N_ROWS / 128, DIM / 128);
    gemm_pool_kernel<<<gA, 256>>>(x, bidx, W1, b1);

    dim3 gB(NSEG / 128, DIM / 128);
    proj_kernel<<<gB, 256>>>(Wp, bp);

    gather_kernel<<<(N_ROWS * 64) / 256, 256>>>(bidx, (float4*)out);
}

// round 3
// speedup vs baseline: 3.3632x; 3.3632x over previous
#include <cuda_runtime.h>
#include <cuda_fp16.h>
#include <cstdint>

#define N_ROWS 524288
#define DIM 256
#define NSEG 8192
#define M_TILES 4096      // N_ROWS / 128
#define GRID_A 148

// ---------------- scratch (device globals) ----------------------------------
__device__ float    g_seg_sum[NSEG * DIM];
__device__ unsigned g_seg_max[NSEG * DIM];
__device__ int      g_counts[NSEG];
__device__ float    g_out_seg[NSEG * DIM];
__device__ __half   g_W1h[DIM * DIM];

// ---------------- helpers ----------------------------------------------------
__device__ __forceinline__ uint32_t smem_u32(const void* p) {
    uint32_t a;
    asm("{ .reg .u64 t; cvta.to.shared.u64 t, %1; cvt.u32.u64 %0, t; }" : "=r"(a) : "l"(p));
    return a;
}
__device__ __forceinline__ void ldmat_x4(uint32_t r[4], uint32_t addr) {
    asm volatile("ldmatrix.sync.aligned.m8n8.x4.shared.b16 {%0,%1,%2,%3}, [%4];"
                 : "=r"(r[0]), "=r"(r[1]), "=r"(r[2]), "=r"(r[3]) : "r"(addr));
}
__device__ __forceinline__ void mma16816(float d[4], const uint32_t a[4],
                                         uint32_t b0, uint32_t b1) {
    asm volatile("mma.sync.aligned.m16n8k16.row.col.f32.f16.f16.f32 "
                 "{%0,%1,%2,%3}, {%4,%5,%6,%7}, {%8,%9}, {%0,%1,%2,%3};"
                 : "+f"(d[0]), "+f"(d[1]), "+f"(d[2]), "+f"(d[3])
                 : "r"(a[0]), "r"(a[1]), "r"(a[2]), "r"(a[3]), "r"(b0), "r"(b1));
}

// order-preserving float <-> uint
__device__ __forceinline__ unsigned enc_f(float f) {
    unsigned i = __float_as_uint(f);
    return (i & 0x80000000u) ? ~i : (i | 0x80000000u);
}
__device__ __forceinline__ float dec_f(unsigned u) {
    return __uint_as_float((u & 0x80000000u) ? (u & 0x7FFFFFFFu) : ~u);
}

// ---------------- smem layout for kernel A (dynamic) ------------------------
// Padded fp16 rows: 264 halves = 528 bytes (conflict-free ldmatrix, 16B aligned)
#define LDH 264
#define ROWB 528u
#define OFF_W    0u                       // 256 * 528 = 135168
#define OFF_A    135168u                  // 128 * 528 = 67584 (reused as hs staging)
#define OFF_BIAS 202752u                  // 256 * 4
#define OFF_SEG  203776u                  // 128 * 4
#define SMEM_A_BYTES 204288

// ---------------- init -------------------------------------------------------
__global__ void init_kernel() {
    int i = blockIdx.x * blockDim.x + threadIdx.x;
    if (i < NSEG * DIM) {
        g_seg_sum[i] = 0.0f;
        g_seg_max[i] = 0u;
    }
    if (i < NSEG) g_counts[i] = 0;
}

// ---------------- W1 fp32 -> fp16 --------------------------------------------
__global__ void wconv_kernel(const float* __restrict__ W1) {
    int i = blockIdx.x * 256 + threadIdx.x;   // over 32768 pairs
    float2 f = ((const float2*)W1)[i];
    __half2 h = __floats2half2_rn(f.x, f.y);
    ((__half2*)g_W1h)[i] = h;
}

// ---------------- kernel A: HMMA GEMM (h = x W1^T + b1) + segmented sum/max -
// persistent, 512 threads = 16 warps in 4x4 grid; warp tile 32(M) x 64(N)
__global__ void __launch_bounds__(512, 1) gemm_pool_mma(
    const float* __restrict__ x,
    const int*   __restrict__ bidx,
    const float* __restrict__ b1)
{
    extern __shared__ char smem[];
    const uint32_t sb = smem_u32(smem);
    const int t    = threadIdx.x;
    const int w    = t >> 5;
    const int lane = t & 31;
    const int wm   = w >> 2;          // 0..3  (M band of 32 rows)
    const int wn   = w & 3;           // 0..3  (N band of 64 cols)

    float*       bias_s = (float*)(smem + OFF_BIAS);
    int*         seg_s  = (int*)(smem + OFF_SEG);
    float*       hs     = (float*)(smem + OFF_A);   // aliases A tile (safe: staged)

    if (t < 256) bias_s[t] = b1[t];

    // ---- W1 fp16 -> SMEM [n][k], padded rows (once per CTA) ----
    {
        const uint4* wsrc = (const uint4*)g_W1h;      // 8192 uint4, 32 per row
#pragma unroll
        for (int j = 0; j < 16; j++) {
            int idx = j * 512 + t;
            int row = idx >> 5, q = idx & 31;
            uint4 v = wsrc[idx];
            uint32_t addr = sb + OFF_W + (uint32_t)row * ROWB + (uint32_t)q * 16u;
            asm volatile("st.shared.v4.b32 [%0], {%1,%2,%3,%4};"
                         :: "r"(addr), "r"(v.x), "r"(v.y), "r"(v.z), "r"(v.w) : "memory");
        }
    }

    // per-thread invariant ldmatrix base offsets: + (lane&15)*row + (lane>>4)*16
    const uint32_t lm_off = (uint32_t)(lane & 15) * ROWB + (uint32_t)(lane >> 4) * 16u;
    const uint32_t a_base = sb + OFF_A + (uint32_t)(wm * 32) * ROWB + lm_off;
    const uint32_t b_base = sb + OFF_W + (uint32_t)(wn * 64) * ROWB + lm_off;

    const float NEG_INF = __int_as_float(0xff800000);

    for (int tile = blockIdx.x; tile < M_TILES; tile += GRID_A) {
        const int rowbase = tile * 128;
        __syncthreads();   // prior epilogue done with hs/seg before overwrite

        if (t < 128) seg_s[t] = bidx[rowbase + t];

        // ---- load x tile fp32 -> fp16 -> SMEM [m][k] padded ----
        {
            const float4* xb4 = (const float4*)(x + (size_t)rowbase * DIM);
#pragma unroll
            for (int j = 0; j < 16; j++) {
                int idx = j * 512 + t;          // over 128*64 float4
                int row = idx >> 6, q = idx & 63;
                float4 v = xb4[idx];
                __half2 h0 = __floats2half2_rn(v.x, v.y);
                __half2 h1 = __floats2half2_rn(v.z, v.w);
                uint32_t addr = sb + OFF_A + (uint32_t)row * ROWB + (uint32_t)q * 8u;
                asm volatile("st.shared.v2.b32 [%0], {%1,%2};"
                             :: "r"(addr), "r"(*(uint32_t*)&h0), "r"(*(uint32_t*)&h1) : "memory");
            }
        }
        __syncthreads();

        // ---- HMMA mainloop: K = 256 in 16 steps of 16 ----
        float acc[2][8][4];
#pragma unroll
        for (int mi = 0; mi < 2; mi++)
#pragma unroll
            for (int ni = 0; ni < 8; ni++)
#pragma unroll
                for (int d = 0; d < 4; d++) acc[mi][ni][d] = 0.0f;

#pragma unroll 4
        for (int ks = 0; ks < 16; ks++) {
            const uint32_t koff = (uint32_t)ks * 32u;
            uint32_t a0[4], a1[4];
            ldmat_x4(a0, a_base + koff);
            ldmat_x4(a1, a_base + 16u * ROWB + koff);
#pragma unroll
            for (int p = 0; p < 4; p++) {
                uint32_t bf[4];
                ldmat_x4(bf, b_base + (uint32_t)p * (16u * ROWB) + koff);
                mma16816(acc[0][2 * p],     a0, bf[0], bf[2]);
                mma16816(acc[0][2 * p + 1], a0, bf[1], bf[3]);
                mma16816(acc[1][2 * p],     a1, bf[0], bf[2]);
                mma16816(acc[1][2 * p + 1], a1, bf[1], bf[3]);
            }
        }

        // ---- epilogue: 4 N-chunks of 64 cols; stage in hs (aliases A) ----
#pragma unroll 1
        for (int ch = 0; ch < 4; ch++) {
            __syncthreads();   // mma reads of A done (ch=0) / prior reduce done
            if (wn == ch) {
                const int r0 = wm * 32 + (lane >> 2);
                const int c0 = 2 * (lane & 3);
#pragma unroll
                for (int mi = 0; mi < 2; mi++)
#pragma unroll
                    for (int ni = 0; ni < 8; ni++) {
                        int col = ni * 8 + c0;
                        float bb0 = bias_s[ch * 64 + col];
                        float bb1 = bias_s[ch * 64 + col + 1];
                        int rr = r0 + mi * 16;
                        hs[rr * 65 + col]           = acc[mi][ni][0] + bb0;
                        hs[rr * 65 + col + 1]       = acc[mi][ni][1] + bb1;
                        hs[(rr + 8) * 65 + col]     = acc[mi][ni][2] + bb0;
                        hs[(rr + 8) * 65 + col + 1] = acc[mi][ni][3] + bb1;
                    }
            }
            __syncthreads();

            // sorted-run segmented reduce: 8 groups x 16 rows, 64 cols
            const int col  = t & 63;
            const int g    = t >> 6;
            const int colG = ch * 64 + col;
            const int r0   = g * 16;
            const bool countLane = (ch == 0) && (col == 0);

            int   cur = seg_s[r0];
            float s   = 0.0f;
            float mx  = NEG_INF;
            int   run = 0;
#pragma unroll 4
            for (int rr = 0; rr < 16; rr++) {
                int   sg = seg_s[r0 + rr];
                float v  = hs[(r0 + rr) * 65 + col];
                if (sg != cur) {
                    atomicAdd(&g_seg_sum[cur * DIM + colG], s);
                    atomicMax(&g_seg_max[cur * DIM + colG], enc_f(mx));
                    if (countLane) atomicAdd(&g_counts[cur], run);
                    cur = sg; s = 0.0f; mx = NEG_INF; run = 0;
                }
                s += v;
                mx = fmaxf(mx, v);
                run++;
            }
            atomicAdd(&g_seg_sum[cur * DIM + colG], s);
            atomicMax(&g_seg_max[cur * DIM + colG], enc_f(mx));
            if (countLane) atomicAdd(&g_counts[cur], run);
        }
    }
}

// ---------------- kernel B: finalize pooled feats + projection GEMM ---------
__global__ __launch_bounds__(256) void proj_kernel(
    const float* __restrict__ Wp,
    const float* __restrict__ bp)
{
    __shared__ float a_s[32 * 128];
    __shared__ float b_s[32 * 128];
    __shared__ float invc[128];
    __shared__ int   cnt[128];

    const int t     = threadIdx.x;
    const int tileM = blockIdx.x * 128;
    const int tileN = blockIdx.y * 128;
    const int tx    = t & 15;
    const int ty    = t >> 4;

    if (t < 128) {
        int cn  = g_counts[tileM + t];
        cnt[t]  = cn;
        invc[t] = 1.0f / (float)max(cn, 1);
    }

    float acc[8][8];
#pragma unroll
    for (int i = 0; i < 8; i++)
#pragma unroll
        for (int j = 0; j < 8; j++) acc[i][j] = 0.0f;

    for (int kt = 0; kt < 2 * DIM; kt += 32) {
        __syncthreads();
#pragma unroll
        for (int l = 0; l < 4; l++) {
            int g4  = l * 256 + t;
            int row = g4 >> 3;
            int kq  = g4 & 7;
            float4 va;
            if (kt < DIM) {
                va = *(const float4*)&g_seg_sum[(size_t)(tileM + row) * DIM + kt + kq * 4];
                float iv = invc[row];
                va.x *= iv; va.y *= iv; va.z *= iv; va.w *= iv;
            } else {
                uint4 u = *(const uint4*)&g_seg_max[(size_t)(tileM + row) * DIM + (kt - DIM) + kq * 4];
                if (cnt[row] > 0) {
                    va.x = dec_f(u.x); va.y = dec_f(u.y); va.z = dec_f(u.z); va.w = dec_f(u.w);
                } else {
                    va.x = va.y = va.z = va.w = 0.0f;
                }
            }
            float4 vb = *(const float4*)&Wp[(size_t)(tileN + row) * (2 * DIM) + kt + kq * 4];
            a_s[(kq * 4 + 0) * 128 + row] = va.x;
            a_s[(kq * 4 + 1) * 128 + row] = va.y;
            a_s[(kq * 4 + 2) * 128 + row] = va.z;
            a_s[(kq * 4 + 3) * 128 + row] = va.w;
            b_s[(kq * 4 + 0) * 128 + row] = vb.x;
            b_s[(kq * 4 + 1) * 128 + row] = vb.y;
            b_s[(kq * 4 + 2) * 128 + row] = vb.z;
            b_s[(kq * 4 + 3) * 128 + row] = vb.w;
        }
        __syncthreads();
#pragma unroll
        for (int kk = 0; kk < 32; kk++) {
            float af[8], bf[8];
            *(float4*)&af[0] = *(const float4*)&a_s[kk * 128 + ty * 8];
            *(float4*)&af[4] = *(const float4*)&a_s[kk * 128 + ty * 8 + 4];
            *(float4*)&bf[0] = *(const float4*)&b_s[kk * 128 + tx * 8];
            *(float4*)&bf[4] = *(const float4*)&b_s[kk * 128 + tx * 8 + 4];
#pragma unroll
            for (int i = 0; i < 8; i++)
#pragma unroll
                for (int j = 0; j < 8; j++)
                    acc[i][j] = fmaf(af[i], bf[j], acc[i][j]);
        }
    }

    float bias[8];
#pragma unroll
    for (int j = 0; j < 8; j++) bias[j] = __ldg(&bp[tileN + tx * 8 + j]);

#pragma unroll
    for (int i = 0; i < 8; i++) {
        float4 v0, v1;
        v0.x = acc[i][0] + bias[0]; v0.y = acc[i][1] + bias[1];
        v0.z = acc[i][2] + bias[2]; v0.w = acc[i][3] + bias[3];
        v1.x = acc[i][4] + bias[4]; v1.y = acc[i][5] + bias[5];
        v1.z = acc[i][6] + bias[6]; v1.w = acc[i][7] + bias[7];
        size_t base = (size_t)(tileM + ty * 8 + i) * DIM + tileN + tx * 8;
        *(float4*)&g_out_seg[base]     = v0;
        *(float4*)&g_out_seg[base + 4] = v1;
    }
}

// ---------------- kernel C: gather with MLP=4 --------------------------------
__global__ void gather_kernel(const int* __restrict__ bidx, float4* __restrict__ out) {
    const int t = threadIdx.x;
    const int base = blockIdx.x * 1024;   // 16 rows x 64 float4
    int seg[4];
#pragma unroll
    for (int i = 0; i < 4; i++) seg[i] = __ldg(&bidx[(base + i * 256 + t) >> 6]);
    float4 v[4];
#pragma unroll
    for (int i = 0; i < 4; i++) {
        int idx = base + i * 256 + t;
        v[i] = ((const float4*)g_out_seg)[seg[i] * 64 + (idx & 63)];
    }
#pragma unroll
    for (int i = 0; i < 4; i++) out[base + i * 256 + t] = v[i];
}

// ---------------- launch -----------------------------------------------------
extern "C" void kernel_launch(void* const* d_in, const int* in_sizes, int n_in,
                              void* d_out, int out_size) {
    const float* x    = (const float*)d_in[0];
    const int*   bidx = (const int*)  d_in[1];
    const float* W1   = (const float*)d_in[2];
    const float* b1   = (const float*)d_in[3];
    const float* Wp   = (const float*)d_in[4];
    const float* bp   = (const float*)d_in[5];
    float* out = (float*)d_out;

    cudaFuncSetAttribute(gemm_pool_mma, cudaFuncAttributeMaxDynamicSharedMemorySize,
                         SMEM_A_BYTES);

    init_kernel<<<(NSEG * DIM + 255) / 256, 256>>>();
    wconv_kernel<<<(DIM * DIM / 2) / 256, 256>>>(W1);

    gemm_pool_mma<<<GRID_A, 512, SMEM_A_BYTES>>>(x, bidx, b1);

    dim3 gB(NSEG / 128, DIM / 128);
    proj_kernel<<<gB, 256>>>(Wp, bp);

    gather_kernel<<<(N_ROWS * 64) / 1024, 256>>>(bidx, (float4*)out);
}